// round 13
// baseline (speedup 1.0000x reference)
#include <cuda_runtime.h>
#include <math.h>

// ---------------------------------------------------------------------------
// RotatedIoULoss — separable Green's-theorem form in the unit box.
// 4 ADJACENT boxes per thread: 20 floats = five aligned float4 loads per
// input array + one float4 weight load. Four independent dependency chains
// per thread for deep ILP; no shared-memory staging.
//
// Coordinates scaled by (1/hw, 1/hh) so box2 = [-1,1]^2. Per edge:
// y-slab window [a,b], x-crossing breakpoints clamped into [a,b],
// 3 trapezoids folded into area2. Degenerate (axis-parallel) edges resolve
// through +/-inf under fmin/fmax/saturate semantics.
// ---------------------------------------------------------------------------

#define IOU_EPS 1e-6f
#define BLOCK 128
#define MAXB  8192

__device__ float g_partial[MAXB];
__device__ unsigned int g_count = 0;   // reset by last block each launch

__device__ __forceinline__ float clamp1(float v) {
    return fminf(fmaxf(v, -1.f), 1.f);
}

__device__ __forceinline__ float box_loss(
    float px, float py, float pw, float ph, float pa,
    float qx, float qy, float qw, float qh, float qa, float w) {

    // frame change into box2's local axes
    float cb, sb; __sincosf(qa, &sb, &cb);
    float dxc = px - qx, dyc = py - qy;
    float ox =  dxc * cb + dyc * sb;
    float oy = -dxc * sb + dyc * cb;
    float cr, sr; __sincosf(pa - qa, &sr, &cr);

    float hw = 0.5f * qw, hh = 0.5f * qh;
    float hx = 0.5f * pw, hy = 0.5f * ph;

    // unit-box scaling: one RCP serves both axes
    float hwh  = hw * hh;
    float ihwh = __fdividef(1.f, hwh);
    float ihw = hh * ihwh, ihh = hw * ihwh;

    float Ox = ox * ihw, Oy = oy * ihh;
    float Ux = (hx * cr) * ihw, Uy = (hx * sr) * ihh;
    float Wx = -(hy * sr) * ihw, Wy = (hy * cr) * ihh;

    // scaled corners (CCW)
    float v0x = Ox + Ux + Wx, v0y = Oy + Uy + Wy;
    float v1x = Ox - Ux + Wx, v1y = Oy - Uy + Wy;
    float v2x = Ox - Ux - Wx, v2y = Oy - Uy - Wy;
    float v3x = Ox + Ux - Wx, v3y = Oy + Uy - Wy;

    // edge dirs: A = v3->v0 = 2W, B = v0->v1 = -2U (C=-A, D=-B)
    float dAx = 2.f * Wx, dAy = 2.f * Wy;
    float dBx = -2.f * Ux, dBy = -2.f * Uy;
    float iAx = __fdividef(1.f, dAx), iAy = __fdividef(1.f, dAy);
    float iBx = __fdividef(1.f, dBx), iBy = __fdividef(1.f, dBy);

    float area2 = 0.f;

#define EDGE(axv, ayv, dx_, dy_, ix_, iy_) do {                        \
        float ta = fmaf((axv), -(ix_), -(ix_));   /* (-1-ax)*ix */     \
        float tb = fmaf((axv), -(ix_),  (ix_));   /* ( 1-ax)*ix */     \
        float tc = fmaf((ayv), -(iy_), -(iy_));                        \
        float td = fmaf((ayv), -(iy_),  (iy_));                        \
        float a_ = __saturatef(fminf(tc, td));                         \
        float b_ = __saturatef(fmaxf(tc, td));                         \
        float t1 = fminf(ta, tb), t2 = fmaxf(ta, tb);                  \
        float c1 = fminf(fmaxf(t1, a_), b_);                           \
        float c2 = fminf(fmaxf(t2, a_), b_);                           \
        float Xa = clamp1(fmaf(a_, (dx_), (axv)));                     \
        float X1 = clamp1(fmaf(c1, (dx_), (axv)));                     \
        float X2 = clamp1(fmaf(c2, (dx_), (axv)));                     \
        float Xb = clamp1(fmaf(b_, (dx_), (axv)));                     \
        float e = Xa * (c1 - a_);                                      \
        e = fmaf(X1, c2 - a_, e);                                      \
        e = fmaf(X2, b_ - c1, e);                                      \
        e = fmaf(Xb, b_ - c2, e);                                      \
        area2 = fmaf((dy_), e, area2);                                 \
    } while (0)

    EDGE(v3x, v3y,  dAx,  dAy,  iAx,  iAy);
    EDGE(v0x, v0y,  dBx,  dBy,  iBx,  iBy);
    EDGE(v1x, v1y, -dAx, -dAy, -iAx, -iAy);
    EDGE(v2x, v2y, -dBx, -dBy, -iBx, -iBy);
#undef EDGE

    float inter = 0.5f * fabsf(area2) * hwh;

    // conservative separation: certain-disjoint -> exact zero (predicated)
    float radx = fabsf(Ux) + fabsf(Wx);
    float rady = fabsf(Uy) + fabsf(Wy);
    bool sep = (fabsf(Ox) > 1.f + radx) || (fabsf(Oy) > 1.f + rady);
    inter = sep ? 0.f : inter;

    float a1 = pw * ph, a2 = qw * qh;
    float iou = __fdividef(inter, a1 + a2 - inter);
    iou = fmaxf(iou, IOU_EPS);
    return -__logf(iou) * w;
}

__global__ void __launch_bounds__(BLOCK, 6)
rl_main(const float* __restrict__ pred,
        const float* __restrict__ target,
        const float* __restrict__ weight,
        float* __restrict__ out,
        int n, int nb, float inv_n) {
    int Tid = blockIdx.x * BLOCK + threadIdx.x;   // quad index
    int i0 = 4 * Tid;                              // first box of the quad

    // box data registers, benign defaults (iou=1, weight 0 -> 0 loss)
    float bx[4][5], tx[4][5], wv[4];
#pragma unroll
    for (int k = 0; k < 4; k++) {
        bx[k][0] = 0.f; bx[k][1] = 0.f; bx[k][2] = 1.f; bx[k][3] = 1.f; bx[k][4] = 0.f;
        tx[k][0] = 0.f; tx[k][1] = 0.f; tx[k][2] = 1.f; tx[k][3] = 1.f; tx[k][4] = 0.f;
        wv[k] = 0.f;
    }

    if (i0 + 3 < n) {
        // fast path: five aligned float4 loads per array + one weight float4
        const float4* p4 = (const float4*)(pred)   + (size_t)Tid * 5;
        const float4* t4 = (const float4*)(target) + (size_t)Tid * 5;
        float4 a0 = p4[0], a1 = p4[1], a2 = p4[2], a3 = p4[3], a4 = p4[4];
        float4 b0 = t4[0], b1 = t4[1], b2 = t4[2], b3 = t4[3], b4 = t4[4];
        float4 ww = ((const float4*)weight)[Tid];
        // layout: [x0 y0 w0 h0][a0 x1 y1 w1][h1 a1 x2 y2][w2 h2 a2 x3][y3 w3 h3 a3]
        bx[0][0]=a0.x; bx[0][1]=a0.y; bx[0][2]=a0.z; bx[0][3]=a0.w; bx[0][4]=a1.x;
        bx[1][0]=a1.y; bx[1][1]=a1.z; bx[1][2]=a1.w; bx[1][3]=a2.x; bx[1][4]=a2.y;
        bx[2][0]=a2.z; bx[2][1]=a2.w; bx[2][2]=a3.x; bx[2][3]=a3.y; bx[2][4]=a3.z;
        bx[3][0]=a3.w; bx[3][1]=a4.x; bx[3][2]=a4.y; bx[3][3]=a4.z; bx[3][4]=a4.w;
        tx[0][0]=b0.x; tx[0][1]=b0.y; tx[0][2]=b0.z; tx[0][3]=b0.w; tx[0][4]=b1.x;
        tx[1][0]=b1.y; tx[1][1]=b1.z; tx[1][2]=b1.w; tx[1][3]=b2.x; tx[1][4]=b2.y;
        tx[2][0]=b2.z; tx[2][1]=b2.w; tx[2][2]=b3.x; tx[2][3]=b3.y; tx[2][4]=b3.z;
        tx[3][0]=b3.w; tx[3][1]=b4.x; tx[3][2]=b4.y; tx[3][3]=b4.z; tx[3][4]=b4.w;
        wv[0]=ww.x; wv[1]=ww.y; wv[2]=ww.z; wv[3]=ww.w;
    } else if (i0 < n) {
        // tail: scalar loads for remaining 1-3 boxes
        for (int k = 0; k < 4; k++) {
            int i = i0 + k;
            if (i < n) {
                const float* P = pred + (size_t)i * 5;
                const float* T = target + (size_t)i * 5;
#pragma unroll
                for (int c = 0; c < 5; c++) { bx[k][c] = P[c]; tx[k][c] = T[c]; }
                wv[k] = weight[i];
            }
        }
    }

    // four independent chains, fully interleavable
    float loss = 0.f;
#pragma unroll
    for (int k = 0; k < 4; k++)
        loss += box_loss(bx[k][0], bx[k][1], bx[k][2], bx[k][3], bx[k][4],
                         tx[k][0], tx[k][1], tx[k][2], tx[k][3], tx[k][4],
                         wv[k]);

    // ---- block reduction -> per-block partial ----
    unsigned mask = 0xFFFFFFFFu;
#pragma unroll
    for (int o = 16; o > 0; o >>= 1)
        loss += __shfl_down_sync(mask, loss, o);

    __shared__ float ws[BLOCK / 32];
    int lane = threadIdx.x & 31;
    int wid = threadIdx.x >> 5;
    if (lane == 0) ws[wid] = loss;
    __syncthreads();
    __shared__ bool is_last;
    if (threadIdx.x == 0) {
        float v = 0.f;
#pragma unroll
        for (int w = 0; w < BLOCK / 32; w++) v += ws[w];
        g_partial[blockIdx.x] = v;
        __threadfence();
        unsigned prev = atomicAdd(&g_count, 1u);
        is_last = (prev == (unsigned)(nb - 1));
    }
    __syncthreads();

    // ---- last block: final reduction (deterministic) ----
    if (is_last) {
        double s = 0.0;
        for (int j = threadIdx.x; j < nb; j += BLOCK)
            s += (double)g_partial[j];
#pragma unroll
        for (int o = 16; o > 0; o >>= 1)
            s += __shfl_down_sync(mask, s, o);
        __shared__ double ds[BLOCK / 32];
        if (lane == 0) ds[wid] = s;
        __syncthreads();
        if (threadIdx.x == 0) {
            double v = 0.0;
#pragma unroll
            for (int w = 0; w < BLOCK / 32; w++) v += ds[w];
            out[0] = (float)(v * (double)inv_n);
            g_count = 0;  // reset for next graph replay
        }
    }
}

extern "C" void kernel_launch(void* const* d_in, const int* in_sizes, int n_in,
                              void* d_out, int out_size) {
    const float* pred   = (const float*)d_in[0];
    const float* target = (const float*)d_in[1];
    const float* weight = (const float*)d_in[2];
    float* out = (float*)d_out;
    int n = in_sizes[2];

    int quads = (n + 3) / 4;
    int grid = (quads + BLOCK - 1) / BLOCK;
    if (grid > MAXB) grid = MAXB;  // n = 1e6 -> 1954 blocks
    rl_main<<<grid, BLOCK>>>(pred, target, weight, out, n, grid,
                             1.0f / (float)n);
}